// round 11
// baseline (speedup 1.0000x reference)
#include <cuda_runtime.h>

// out[i,o,n] = 4-tap conv over x's last axis with 64->64 channel mix, plus two
// circular rolls (n -> (n-1)%56 input remap; o=0 wrap correction on arm 2).
//
// x: (1, 64, 56, 56) float32  -> x[j*3136 + n*56 + l]
// W: (64, 3, 2, 64)  float32  -> W[i*384 + k*128 + l2*64 + j]
// out: (1, 64, 56, 56) float32
//
// Block = 224 threads, grid (56 n, 8 i-groups).
// Prologue is ONE phase, warp-specialized:
//   warps 0-3: W -> registers -> folded weights (sV/sC) + zero guards
//   warps 4-6: x slice -> sX (batched LDG.128, aligned STS.64)
// Mainloop: (il2 in 4 i-pairs) x (seg in 7 o-octets) x (jq in 8 j-slices),
// each thread 2 i x 8 o x 8 channels with LDS.128 x-window reuse.

#define NROW 60   // c = l + 2; guards c in {0,1,58,59} are zero

__global__ __launch_bounds__(224, 4)
void shiftconv_kernel(const float* __restrict__ x,
                      const float* __restrict__ W,
                      float* __restrict__ out)
{
    __shared__ __align__(16) float  sX[64][NROW];
    __shared__ __align__(16) float4 sV[64][9];   // [j][il] = (V-2, V-1, V0, V+1), padded row
    __shared__ __align__(16) float2 sC[64][8];   // [j][il] = (W[i,1,1,j], W[i,2,1,j])
    __shared__ __align__(16) float  sP[8][28][20]; // partials [jq][seg*4+il2][a*8+t]

    const int tid = threadIdx.x;
    const int n   = blockIdx.x;          // output column
    const int ig  = blockIdx.y;          // i-group of 8
    const int np  = (n + 55) % 56;       // (n-1) mod 56  (final roll along axis 3)

    // ================= single-phase prologue =================
    if (tid < 128) {
        // ---- W path: one (il, j4) item, transform in registers ----
        const int il = tid >> 4;                 // 0..7
        const int j4 = tid & 15;                 // 0..15 (j = 4*j4 .. +3)
        // W4 index: i*96 + k*32 + l2*16 + j4  (float4 units)
        const float4* Wb = (const float4*)W + ig * 768 + il * 96 + j4;
        const float4 A0 = Wb[0];    // w00 (k=0,l2=0)
        const float4 A1 = Wb[16];   // w01
        const float4 A2 = Wb[32];   // w10
        const float4 A3 = Wb[48];   // w11
        const float4 A4 = Wb[64];   // w20
        const float4 A5 = Wb[80];   // w21
        const int j = j4 * 4;
        sV[j + 0][il] = make_float4(A1.x, A0.x + A3.x, A2.x + A5.x, A4.x);
        sV[j + 1][il] = make_float4(A1.y, A0.y + A3.y, A2.y + A5.y, A4.y);
        sV[j + 2][il] = make_float4(A1.z, A0.z + A3.z, A2.z + A5.z, A4.z);
        sV[j + 3][il] = make_float4(A1.w, A0.w + A3.w, A2.w + A5.w, A4.w);
        sC[j + 0][il] = make_float2(A3.x, A5.x);
        sC[j + 1][il] = make_float2(A3.y, A5.y);
        sC[j + 2][il] = make_float2(A3.z, A5.z);
        sC[j + 3][il] = make_float2(A3.w, A5.w);
        // ---- guards: c in {0,1,58,59} = 0 for all 64 j (2 per thread) ----
        #pragma unroll
        for (int g = 0; g < 2; g++) {
            const int idx = tid * 2 + g;         // 0..255
            const int jj  = idx >> 2, gg = idx & 3;
            sX[jj][(gg & 1) + (gg >> 1) * 58] = 0.0f;
        }
    } else {
        // ---- x path: 96 threads, 896 float4 loads, batched for MLP ----
        const int t = tid - 128;                 // 0..95
        const float4* X4 = (const float4*)x;
        float4 g[10];
        #pragma unroll
        for (int q = 0; q < 10; q++) {
            const int f = t + 96 * q;            // q<9 always <896; q=9 iff t<32
            if (f < 896) {
                const int j = f / 14, r = f % 14;
                g[q] = X4[j * 784 + np * 14 + r];
            }
        }
        #pragma unroll
        for (int q = 0; q < 10; q++) {
            const int f = t + 96 * q;
            if (f < 896) {
                const int j = f / 14, r = f % 14;
                float* d = &sX[j][2 + 4 * r];    // 8B aligned
                *(float2*)(d)     = make_float2(g[q].x, g[q].y);
                *(float2*)(d + 2) = make_float2(g[q].z, g[q].w);
            }
        }
    }
    __syncthreads();

    // ================= mainloop =================
    const int il2 = tid & 3;             // i-pair index (i = ig*8 + 2*il2 + {0,1})
    const int seg = (tid >> 2) % 7;      // o octet (0..6)
    const int jq  = tid / 28;            // j slice (0..7)
    const int ob  = seg * 8;
    const int j0  = jq * 8;

    float a0[8], a1[8];
    #pragma unroll
    for (int t = 0; t < 8; t++) { a0[t] = 0.0f; a1[t] = 0.0f; }

    #pragma unroll
    for (int jj = 0; jj < 8; jj++) {
        const int j = j0 + jj;
        // window c = ob..ob+11 (o = ob..ob+7, taps d in [-2,1]) : 3 aligned float4
        const float4* xr = (const float4*)&sX[j][ob];
        const float4 xa = xr[0], xb = xr[1], xc = xr[2];
        const float xv[12] = {xa.x, xa.y, xa.z, xa.w, xb.x, xb.y, xb.z, xb.w,
                              xc.x, xc.y, xc.z, xc.w};
        const float4 v0 = sV[j][il2 * 2];
        const float4 v1 = sV[j][il2 * 2 + 1];
        #pragma unroll
        for (int t = 0; t < 8; t++) {
            a0[t] = fmaf(xv[t],     v0.x,
                    fmaf(xv[t + 1], v0.y,
                    fmaf(xv[t + 2], v0.z,
                    fmaf(xv[t + 3], v0.w, a0[t]))));
            a1[t] = fmaf(xv[t],     v1.x,
                    fmaf(xv[t + 1], v1.y,
                    fmaf(xv[t + 2], v1.z,
                    fmaf(xv[t + 3], v1.w, a1[t]))));
        }
        // o = 0 wrap on the second unfold arm:
        // add x[54]*W[i,0,1] + x[55]*W[i,1,1], remove the wrong x[0]*W[i,2,1]
        if (seg == 0) {
            const float2 c0 = sC[j][il2 * 2];
            const float2 c1 = sC[j][il2 * 2 + 1];
            const float x54 = sX[j][56], x55 = sX[j][57], x00 = sX[j][2];
            a0[0] = fmaf(x54, v0.x, fmaf(x55, c0.x, fmaf(-x00, c0.y, a0[0])));
            a1[0] = fmaf(x54, v1.x, fmaf(x55, c1.x, fmaf(-x00, c1.y, a1[0])));
        }
    }

    // ---- park partials (no alias with prologue buffers -> no extra barrier) ----
    {
        float4* pr = (float4*)&sP[jq][seg * 4 + il2][0];
        pr[0] = make_float4(a0[0], a0[1], a0[2], a0[3]);
        pr[1] = make_float4(a0[4], a0[5], a0[6], a0[7]);
        pr[2] = make_float4(a1[0], a1[1], a1[2], a1[3]);
        pr[3] = make_float4(a1[4], a1[5], a1[6], a1[7]);
    }
    __syncthreads();

    // ---- fully parallel reduction + store: 448 outputs, 2 per thread ----
    #pragma unroll
    for (int q2 = 0; q2 < 2; q2++) {
        const int q     = tid + 224 * q2;    // 0..447
        const int i_loc = q & 7;
        const int o     = q >> 3;
        const int row   = (o >> 3) * 4 + (i_loc >> 1);
        const int col   = (i_loc & 1) * 8 + (o & 7);
        float s = 0.0f;
        #pragma unroll
        for (int sj = 0; sj < 8; sj++) s += sP[sj][row][col];
        out[(ig * 8 + i_loc) * 3136 + o * 56 + n] = s;
    }
}

extern "C" void kernel_launch(void* const* d_in, const int* in_sizes, int n_in,
                              void* d_out, int out_size)
{
    const float* x = (const float*)d_in[0];
    const float* W = (const float*)d_in[1];
    float* out = (float*)d_out;
    (void)in_sizes; (void)n_in; (void)out_size;

    dim3 grid(56, 8);
    shiftconv_kernel<<<grid, 224>>>(x, W, out);
}

// round 12
// speedup vs baseline: 1.0029x; 1.0029x over previous
#include <cuda_runtime.h>

// out[i,o,n] = 4-tap conv over x's last axis with 64->64 channel mix, plus two
// circular rolls (n -> (n-1)%56 input remap; o=0 wrap correction on arm 2).
//
// x: (1, 64, 56, 56) float32  -> x[j*3136 + n*56 + l]
// W: (64, 3, 2, 64)  float32  -> W[i*384 + k*128 + l2*64 + j]
// out: (1, 64, 56, 56) float32
//
// Block = 224 threads, grid (56 n, 8 i-groups).
// Mainloop uses packed fma.rn.f32x2 (FFMA2): each thread's two output channels
// (i-pair) live in the two fp32 lanes of 64-bit accumulators. Weight pairs are
// pre-interleaved in smem so one LDS.128 yields two packed operands.

#define NROW 60   // c = l + 2; guards c in {0,1,58,59} are zero

__device__ __forceinline__ unsigned long long dup2(float v) {
    unsigned long long r;
    asm("mov.b64 %0, {%1, %1};" : "=l"(r) : "f"(v));
    return r;
}
__device__ __forceinline__ void fma2(unsigned long long& d,
                                     unsigned long long a, unsigned long long b) {
    asm("fma.rn.f32x2 %0, %1, %2, %0;" : "+l"(d) : "l"(a), "l"(b));
}
__device__ __forceinline__ float2 unpk2(unsigned long long v) {
    float2 r;
    asm("mov.b64 {%0, %1}, %2;" : "=f"(r.x), "=f"(r.y) : "l"(v));
    return r;
}

__global__ __launch_bounds__(224, 3)
void shiftconv_kernel(const float* __restrict__ x,
                      const float* __restrict__ W,
                      float* __restrict__ out)
{
    __shared__ __align__(16) float      sX[64][NROW];
    // sVp[j][il2*2+h]: h=0 -> lanes {(V-2 i0,V-2 i1),(V-1 i0,V-1 i1)}
    //                  h=1 -> lanes {(V0 pair),(V+1 pair)}
    __shared__ __align__(16) ulonglong2 sVp[64][8];
    // sCp[j][il2]: lanes {(W11 i0,W11 i1),(W21 i0,W21 i1)}
    __shared__ __align__(16) ulonglong2 sCp[64][4];
    __shared__ __align__(16) float      sP[8][28][20]; // partials [jq][seg*4+il2][a*8+t]

    const int tid = threadIdx.x;
    const int n   = blockIdx.x;          // output column
    const int ig  = blockIdx.y;          // i-group of 8
    const int np  = (n + 55) % 56;       // (n-1) mod 56  (final roll along axis 3)

    // ================= single-phase warp-specialized prologue =================
    if (tid < 64) {
        // ---- W path: one (il2, j4) item, BOTH i-rows, transform in registers ----
        const int il2 = tid >> 4;                // 0..3
        const int j4  = tid & 15;                // 0..15 (j = 4*j4 .. +3)
        const int i0  = ig * 8 + il2 * 2;
        const float4* Wa = (const float4*)W + i0 * 96 + j4;        // row i0
        const float4* Wb = Wa + 96;                                // row i0+1
        const float4 A0 = Wa[0],  A1 = Wa[16], A2 = Wa[32];
        const float4 A3 = Wa[48], A4 = Wa[64], A5 = Wa[80];
        const float4 B0 = Wb[0],  B1 = Wb[16], B2 = Wb[32];
        const float4 B3 = Wb[48], B4 = Wb[64], B5 = Wb[80];
        const int j = j4 * 4;
        float4* v0 = (float4*)&sVp[j][il2 * 2];          // j+0
        float4* v1 = (float4*)&sVp[j + 1][il2 * 2];
        float4* v2 = (float4*)&sVp[j + 2][il2 * 2];
        float4* v3 = (float4*)&sVp[j + 3][il2 * 2];
        v0[0] = make_float4(A1.x, B1.x, A0.x + A3.x, B0.x + B3.x);
        v0[1] = make_float4(A2.x + A5.x, B2.x + B5.x, A4.x, B4.x);
        v1[0] = make_float4(A1.y, B1.y, A0.y + A3.y, B0.y + B3.y);
        v1[1] = make_float4(A2.y + A5.y, B2.y + B5.y, A4.y, B4.y);
        v2[0] = make_float4(A1.z, B1.z, A0.z + A3.z, B0.z + B3.z);
        v2[1] = make_float4(A2.z + A5.z, B2.z + B5.z, A4.z, B4.z);
        v3[0] = make_float4(A1.w, B1.w, A0.w + A3.w, B0.w + B3.w);
        v3[1] = make_float4(A2.w + A5.w, B2.w + B5.w, A4.w, B4.w);
        *(float4*)&sCp[j][il2]     = make_float4(A3.x, B3.x, A5.x, B5.x);
        *(float4*)&sCp[j + 1][il2] = make_float4(A3.y, B3.y, A5.y, B5.y);
        *(float4*)&sCp[j + 2][il2] = make_float4(A3.z, B3.z, A5.z, B5.z);
        *(float4*)&sCp[j + 3][il2] = make_float4(A3.w, B3.w, A5.w, B5.w);
    } else if (tid < 96) {
        // ---- guards: c in {0,1,58,59} = 0 for all 64 j ----
        const int t = tid - 64;                  // 0..31
        #pragma unroll
        for (int g = 0; g < 8; g++) {
            const int idx = t * 8 + g;           // 0..255
            const int jj  = idx >> 2, gg = idx & 3;
            sX[jj][(gg & 1) + (gg >> 1) * 58] = 0.0f;
        }
    } else {
        // ---- x path: 128 threads, 896 float4 loads, batched for MLP ----
        const int t = tid - 96;                  // 0..127
        const float4* X4 = (const float4*)x;
        float4 g[7];
        #pragma unroll
        for (int q = 0; q < 7; q++) {
            const int f = t + 128 * q;           // f<896 full
            const int j = f / 14, r = f % 14;
            g[q] = X4[j * 784 + np * 14 + r];
        }
        #pragma unroll
        for (int q = 0; q < 7; q++) {
            const int f = t + 128 * q;
            const int j = f / 14, r = f % 14;
            float* d = &sX[j][2 + 4 * r];        // 8B aligned
            *(float2*)(d)     = make_float2(g[q].x, g[q].y);
            *(float2*)(d + 2) = make_float2(g[q].z, g[q].w);
        }
    }
    __syncthreads();

    // ================= mainloop (packed f32x2) =================
    const int il2 = tid & 3;             // i-pair index (i = ig*8 + 2*il2 + {0,1})
    const int seg = (tid >> 2) % 7;      // o octet (0..6)
    const int jq  = tid / 28;            // j slice (0..7)
    const int ob  = seg * 8;
    const int j0  = jq * 8;

    unsigned long long acc[8];
    #pragma unroll
    for (int t = 0; t < 8; t++) acc[t] = 0ULL;

    #pragma unroll
    for (int jj = 0; jj < 8; jj++) {
        const int j = j0 + jj;
        // window c = ob..ob+11 (o = ob..ob+7, taps d in [-2,1]) : 3 aligned float4
        const float4* xr = (const float4*)&sX[j][ob];
        const float4 xa = xr[0], xb = xr[1], xc = xr[2];
        const float xv[12] = {xa.x, xa.y, xa.z, xa.w, xb.x, xb.y, xb.z, xb.w,
                              xc.x, xc.y, xc.z, xc.w};
        unsigned long long xd[12];
        #pragma unroll
        for (int k = 0; k < 12; k++) xd[k] = dup2(xv[k]);

        const ulonglong2 vA = sVp[j][il2 * 2];       // .x = V-2 pair, .y = V-1 pair
        const ulonglong2 vB = sVp[j][il2 * 2 + 1];   // .x = V0 pair,  .y = V+1 pair
        #pragma unroll
        for (int t = 0; t < 8; t++) {
            fma2(acc[t], xd[t],     vA.x);
            fma2(acc[t], xd[t + 1], vA.y);
            fma2(acc[t], xd[t + 2], vB.x);
            fma2(acc[t], xd[t + 3], vB.y);
        }
        // o = 0 wrap on the second unfold arm:
        // add x[54]*W[i,0,1] + x[55]*W[i,1,1], remove the wrong x[0]*W[i,2,1]
        if (seg == 0) {
            const ulonglong2 cp = sCp[j][il2];       // .x = W11 pair, .y = W21 pair
            fma2(acc[0], dup2(sX[j][56]),  vA.x);    // x[54] * W01 (== V-2)
            fma2(acc[0], dup2(sX[j][57]),  cp.x);    // x[55] * W11
            fma2(acc[0], dup2(-sX[j][2]),  cp.y);    // -x[0] * W21
        }
    }

    // ---- unpack + park partials ----
    {
        float a0[8], a1[8];
        #pragma unroll
        for (int t = 0; t < 8; t++) {
            const float2 p = unpk2(acc[t]);
            a0[t] = p.x; a1[t] = p.y;
        }
        float4* pr = (float4*)&sP[jq][seg * 4 + il2][0];
        pr[0] = make_float4(a0[0], a0[1], a0[2], a0[3]);
        pr[1] = make_float4(a0[4], a0[5], a0[6], a0[7]);
        pr[2] = make_float4(a1[0], a1[1], a1[2], a1[3]);
        pr[3] = make_float4(a1[4], a1[5], a1[6], a1[7]);
    }
    __syncthreads();

    // ---- fully parallel reduction + store: 448 outputs, 2 per thread ----
    #pragma unroll
    for (int q2 = 0; q2 < 2; q2++) {
        const int q     = tid + 224 * q2;    // 0..447
        const int i_loc = q & 7;
        const int o     = q >> 3;
        const int row   = (o >> 3) * 4 + (i_loc >> 1);
        const int col   = (i_loc & 1) * 8 + (o & 7);
        float s = 0.0f;
        #pragma unroll
        for (int sj = 0; sj < 8; sj++) s += sP[sj][row][col];
        out[(ig * 8 + i_loc) * 3136 + o * 56 + n] = s;
    }
}

extern "C" void kernel_launch(void* const* d_in, const int* in_sizes, int n_in,
                              void* d_out, int out_size)
{
    const float* x = (const float*)d_in[0];
    const float* W = (const float*)d_in[1];
    float* out = (float*)d_out;
    (void)in_sizes; (void)n_in; (void)out_size;

    dim3 grid(56, 8);
    shiftconv_kernel<<<grid, 224>>>(x, W, out);
}

// round 13
// speedup vs baseline: 1.0650x; 1.0619x over previous
#include <cuda_runtime.h>

// out[i,o,n] = 4-tap conv over x's last axis with 64->64 channel mix, plus two
// circular rolls (n -> (n-1)%56 input remap; o=0 wrap correction on arm 2).
//
// x: (1, 64, 56, 56) float32  -> x[j*3136 + n*56 + l]
// W: (64, 3, 2, 64)  float32  -> W[i*384 + k*128 + l2*64 + j]
// out: (1, 64, 56, 56) float32
//
// Grid (14, 8): each block = 4 consecutive n-columns x one i-group of 8.
// 448 threads = (il2 in 4 i-pairs) x (seg in 7 o-octets) x (jq in 8 j-slices)
//             x (nh in 2): thread handles columns nh and nh+2, sharing weights.
// Packed fma.rn.f32x2: i-pair lives in the two fp32 lanes of 64-bit accs.
// Epilogue: one float4 STG per thread spanning the 4 n-columns (coalesced).

#define OFF_X 0                      // float sX[4][64][60]   = 61440 B
#define OFF_V 61440                  // ulonglong2 sVp[64][8] =  8192 B
#define OFF_C 69632                  // ulonglong2 sCp[64][4] =  4096 B
#define OFF_P 0                      // float sP[4][8][28][20] (aliases X/V/C)
#define SMEM_TOTAL 73728

__device__ __forceinline__ unsigned long long dup2(float v) {
    unsigned long long r;
    asm("mov.b64 %0, {%1, %1};" : "=l"(r) : "f"(v));
    return r;
}
__device__ __forceinline__ void fma2(unsigned long long& d,
                                     unsigned long long a, unsigned long long b) {
    asm("fma.rn.f32x2 %0, %1, %2, %0;" : "+l"(d) : "l"(a), "l"(b));
}
__device__ __forceinline__ float2 unpk2(unsigned long long v) {
    float2 r;
    asm("mov.b64 {%0, %1}, %2;" : "=f"(r.x), "=f"(r.y) : "l"(v));
    return r;
}

__global__ __launch_bounds__(448, 1)
void shiftconv_kernel(const float* __restrict__ x,
                      const float* __restrict__ W,
                      float* __restrict__ out)
{
    extern __shared__ __align__(16) char smem[];
    float      (*sX)[64][60]     = (float (*)[64][60])(smem + OFF_X);
    ulonglong2 (*sVp)[8]         = (ulonglong2 (*)[8])(smem + OFF_V);
    ulonglong2 (*sCp)[4]         = (ulonglong2 (*)[4])(smem + OFF_C);
    float      (*sP)[8][28][20]  = (float (*)[8][28][20])(smem + OFF_P);

    const int tid = threadIdx.x;
    const int n0  = blockIdx.x * 4;      // first of 4 output columns
    const int ig  = blockIdx.y;          // i-group of 8

    int npc[4];
    #pragma unroll
    for (int c = 0; c < 4; c++) npc[c] = (n0 + c + 55) % 56;

    // ================= prologue =================
    // W loads issue first (2 warps), x loads from ALL threads right behind.
    float4 A0, A1, A2, A3, A4, A5, B0, B1, B2, B3, B4, B5;
    if (tid < 64) {
        const int il2 = tid >> 4;                // 0..3
        const int j4  = tid & 15;                // 0..15
        const int i0  = ig * 8 + il2 * 2;
        const float4* Wa = (const float4*)W + i0 * 96 + j4;
        const float4* Wb = Wa + 96;
        A0 = Wa[0];  A1 = Wa[16]; A2 = Wa[32];
        A3 = Wa[48]; A4 = Wa[64]; A5 = Wa[80];
        B0 = Wb[0];  B1 = Wb[16]; B2 = Wb[32];
        B3 = Wb[48]; B4 = Wb[64]; B5 = Wb[80];
    }

    // x: 4 columns x 896 float4 = 3584 vector loads; 8 per thread, batched.
    const float4* X4 = (const float4*)x;
    float4 g[8];
    #pragma unroll
    for (int q = 0; q < 8; q++) {
        const int f  = tid + 448 * q;    // 0..3583
        const int c  = f / 896;
        const int rr = f % 896;
        const int j  = rr / 14, r = rr % 14;
        g[q] = X4[j * 784 + npc[c] * 14 + r];
    }
    #pragma unroll
    for (int q = 0; q < 8; q++) {
        const int f  = tid + 448 * q;
        const int c  = f / 896;
        const int rr = f % 896;
        const int j  = rr / 14, r = rr % 14;
        float* d = &sX[c][j][2 + 4 * r];         // 8B aligned
        *(float2*)(d)     = make_float2(g[q].x, g[q].y);
        *(float2*)(d + 2) = make_float2(g[q].z, g[q].w);
    }

    if (tid < 64) {
        // fold 6 taps -> 4 packed i-pair weights; keep W11/W21 pairs for o=0 wrap
        const int il2 = tid >> 4;
        const int j   = (tid & 15) * 4;
        float4* v0 = (float4*)&sVp[j][il2 * 2];
        float4* v1 = (float4*)&sVp[j + 1][il2 * 2];
        float4* v2 = (float4*)&sVp[j + 2][il2 * 2];
        float4* v3 = (float4*)&sVp[j + 3][il2 * 2];
        v0[0] = make_float4(A1.x, B1.x, A0.x + A3.x, B0.x + B3.x);
        v0[1] = make_float4(A2.x + A5.x, B2.x + B5.x, A4.x, B4.x);
        v1[0] = make_float4(A1.y, B1.y, A0.y + A3.y, B0.y + B3.y);
        v1[1] = make_float4(A2.y + A5.y, B2.y + B5.y, A4.y, B4.y);
        v2[0] = make_float4(A1.z, B1.z, A0.z + A3.z, B0.z + B3.z);
        v2[1] = make_float4(A2.z + A5.z, B2.z + B5.z, A4.z, B4.z);
        v3[0] = make_float4(A1.w, B1.w, A0.w + A3.w, B0.w + B3.w);
        v3[1] = make_float4(A2.w + A5.w, B2.w + B5.w, A4.w, B4.w);
        *(float4*)&sCp[j][il2]     = make_float4(A3.x, B3.x, A5.x, B5.x);
        *(float4*)&sCp[j + 1][il2] = make_float4(A3.y, B3.y, A5.y, B5.y);
        *(float4*)&sCp[j + 2][il2] = make_float4(A3.z, B3.z, A5.z, B5.z);
        *(float4*)&sCp[j + 3][il2] = make_float4(A3.w, B3.w, A5.w, B5.w);
    } else {
        // guards: sX[c][j][{0,1,58,59}] = 0  (1024 writes over 384 threads)
        const int t = tid - 64;
        #pragma unroll
        for (int g3 = 0; g3 < 3; g3++) {
            const int p = t + 384 * g3;
            if (p < 1024) {
                const int c = p >> 8, idx = p & 255;
                const int j = idx >> 2, gg = idx & 3;
                sX[c][j][(gg & 1) + (gg >> 1) * 58] = 0.0f;
            }
        }
    }
    __syncthreads();

    // ================= mainloop (2 columns per thread, shared weights) ====
    const int il2 = tid & 3;
    const int seg = (tid >> 2) % 7;
    const int jq  = (tid / 28) % 8;
    const int nh  = tid / 224;           // 0 or 1
    const int ob  = seg * 8;
    const int j0  = jq * 8;
    const int cA  = nh, cB = nh + 2;

    unsigned long long accA[8], accB[8];
    #pragma unroll
    for (int t = 0; t < 8; t++) { accA[t] = 0ULL; accB[t] = 0ULL; }

    #pragma unroll
    for (int jj = 0; jj < 8; jj++) {
        const int j = j0 + jj;
        const ulonglong2 vA = sVp[j][il2 * 2];       // V-2 pair, V-1 pair
        const ulonglong2 vB = sVp[j][il2 * 2 + 1];   // V0 pair,  V+1 pair

        // column A
        {
            const float4* xr = (const float4*)&sX[cA][j][ob];
            const float4 xa = xr[0], xb = xr[1], xc = xr[2];
            const float xv[12] = {xa.x, xa.y, xa.z, xa.w, xb.x, xb.y, xb.z, xb.w,
                                  xc.x, xc.y, xc.z, xc.w};
            unsigned long long xd[12];
            #pragma unroll
            for (int k = 0; k < 12; k++) xd[k] = dup2(xv[k]);
            #pragma unroll
            for (int t = 0; t < 8; t++) {
                fma2(accA[t], xd[t],     vA.x);
                fma2(accA[t], xd[t + 1], vA.y);
                fma2(accA[t], xd[t + 2], vB.x);
                fma2(accA[t], xd[t + 3], vB.y);
            }
        }
        // column B
        {
            const float4* xr = (const float4*)&sX[cB][j][ob];
            const float4 xa = xr[0], xb = xr[1], xc = xr[2];
            const float xv[12] = {xa.x, xa.y, xa.z, xa.w, xb.x, xb.y, xb.z, xb.w,
                                  xc.x, xc.y, xc.z, xc.w};
            unsigned long long xd[12];
            #pragma unroll
            for (int k = 0; k < 12; k++) xd[k] = dup2(xv[k]);
            #pragma unroll
            for (int t = 0; t < 8; t++) {
                fma2(accB[t], xd[t],     vA.x);
                fma2(accB[t], xd[t + 1], vA.y);
                fma2(accB[t], xd[t + 2], vB.x);
                fma2(accB[t], xd[t + 3], vB.y);
            }
        }
        // o = 0 wrap on the second unfold arm:
        // add x[54]*W[i,0,1] + x[55]*W[i,1,1], remove the wrong x[0]*W[i,2,1]
        if (seg == 0) {
            const ulonglong2 cp = sCp[j][il2];       // W11 pair, W21 pair
            fma2(accA[0], dup2(sX[cA][j][56]), vA.x);
            fma2(accA[0], dup2(sX[cA][j][57]), cp.x);
            fma2(accA[0], dup2(-sX[cA][j][2]), cp.y);
            fma2(accB[0], dup2(sX[cB][j][56]), vA.x);
            fma2(accB[0], dup2(sX[cB][j][57]), cp.x);
            fma2(accB[0], dup2(-sX[cB][j][2]), cp.y);
        }
    }

    // ---- barrier, then park partials into the aliased buffer ----
    __syncthreads();
    {
        float a0[8], a1[8];
        #pragma unroll
        for (int t = 0; t < 8; t++) {
            const float2 p = unpk2(accA[t]);
            a0[t] = p.x; a1[t] = p.y;
        }
        float4* pr = (float4*)&sP[cA][jq][seg * 4 + il2][0];
        pr[0] = make_float4(a0[0], a0[1], a0[2], a0[3]);
        pr[1] = make_float4(a0[4], a0[5], a0[6], a0[7]);
        pr[2] = make_float4(a1[0], a1[1], a1[2], a1[3]);
        pr[3] = make_float4(a1[4], a1[5], a1[6], a1[7]);
        #pragma unroll
        for (int t = 0; t < 8; t++) {
            const float2 p = unpk2(accB[t]);
            a0[t] = p.x; a1[t] = p.y;
        }
        pr = (float4*)&sP[cB][jq][seg * 4 + il2][0];
        pr[0] = make_float4(a0[0], a0[1], a0[2], a0[3]);
        pr[1] = make_float4(a0[4], a0[5], a0[6], a0[7]);
        pr[2] = make_float4(a1[0], a1[1], a1[2], a1[3]);
        pr[3] = make_float4(a1[4], a1[5], a1[6], a1[7]);
    }
    __syncthreads();

    // ---- reduction + coalesced float4 store: one (i,o) x 4 n per thread ----
    {
        const int i_loc = tid & 7;
        const int o     = tid >> 3;          // 0..55
        const int row   = (o >> 3) * 4 + (i_loc >> 1);
        const int col   = (i_loc & 1) * 8 + (o & 7);
        float4 s = make_float4(0.f, 0.f, 0.f, 0.f);
        #pragma unroll
        for (int sj = 0; sj < 8; sj++) {
            s.x += sP[0][sj][row][col];
            s.y += sP[1][sj][row][col];
            s.z += sP[2][sj][row][col];
            s.w += sP[3][sj][row][col];
        }
        *(float4*)&out[(ig * 8 + i_loc) * 3136 + o * 56 + n0] = s;
    }
}

extern "C" void kernel_launch(void* const* d_in, const int* in_sizes, int n_in,
                              void* d_out, int out_size)
{
    const float* x = (const float*)d_in[0];
    const float* W = (const float*)d_in[1];
    float* out = (float*)d_out;
    (void)in_sizes; (void)n_in; (void)out_size;

    cudaFuncSetAttribute(shiftconv_kernel,
                         cudaFuncAttributeMaxDynamicSharedMemorySize, SMEM_TOTAL);
    dim3 grid(14, 8);
    shiftconv_kernel<<<grid, 448, SMEM_TOTAL>>>(x, W, out);
}